// round 6
// baseline (speedup 1.0000x reference)
#include <cuda_runtime.h>

typedef unsigned long long ull;

#define ETH 128
#define HTH 256
#define M_FLOATS (64*320)
#define M1_FLOATS (64*256)
#define M2_FLOATS (64*64)
#define W1_FLOATS (64*16)
#define N_NODES 25000
#define E_MAX 400000

__device__ float  g_M1[M1_FLOATS];            // [m][sect4:{A,B,C,E}][u][w]  (L1-resident)
__device__ float  g_M2[M2_FLOATS];            // [m][u][w]  D' = D - E/3    (L1-resident)
__device__ float  g_W1t[W1_FLOATS];           // [m][16] W1^T / 4
__device__ double g_acc[N_NODES * 32];        // segment-sum accumulator
__device__ float  g_hp[8][(size_t)E_MAX * 8]; // [chunk][e*8+mm] radial MLP outputs
__device__ float4 g_n[E_MAX];                 // unit edge vectors

__device__ __forceinline__ ull pk2(float a, float b){ ull r; asm("mov.b64 %0, {%1,%2};" : "=l"(r) : "f"(a), "f"(b)); return r; }
__device__ __forceinline__ ull fma2(ull a, ull b, ull c){ ull d; asm("fma.rn.f32x2 %0, %1, %2, %3;" : "=l"(d) : "l"(a), "l"(b), "l"(c)); return d; }
__device__ __forceinline__ ull mul2(ull a, ull b){ ull d; asm("mul.rn.f32x2 %0, %1, %2;" : "=l"(d) : "l"(a), "l"(b)); return d; }
__device__ __forceinline__ float2 upk(ull a){ float2 f; asm("mov.b64 {%0,%1}, %2;" : "=f"(f.x), "=f"(f.y) : "l"(a)); return f; }

// ---------------- prep: fold W2 + scales into M1/M2 ----------------
__global__ void prep_kernel(const float* __restrict__ W1, const float* __restrict__ W2)
{
    int idx = blockIdx.x * blockDim.x + threadIdx.x;
    const float a0  = 0.17677669529663687f;   // 1/sqrt(32)
    const float a1  = 0.27386127875258304f;   // sqrt(3/40)
    const float a1s = 0.15811388300841897f;   // a1/sqrt(3)
    const float aE  = 0.33541019662496846f;   // a1*sqrt(1.5)
    if (idx < M_FLOATS) {
        int m = idx / 320, o = idx % 320;
        int sect = o >> 6, r = o & 63, u = r >> 3, w = r & 7;
        const float* Vm = W2 + m * 576;
        float eval = aE * 0.125f * Vm[512 + u * 8 + w];
        float val;
        if (sect < 4) {
            int t0 = sect * 128 + u * 16 + w;
            float s = (sect <= 1) ? a0 : (sect == 2 ? a1 : a1s);
            val = s * 0.125f * (Vm[t0] + Vm[t0 + 8]);
            if (sect == 3) val -= eval * (1.0f / 3.0f);   // fold -E/3 into D
        } else {
            val = eval;
        }
        if (sect == 3) {
            g_M2[m * 64 + u * 8 + w] = val;
        } else {
            int s4 = (sect == 4) ? 3 : sect;   // {A,B,C,E}
            g_M1[m * 256 + s4 * 64 + u * 8 + w] = val;
        }
    }
    if (idx < W1_FLOATS) {
        int m = idx >> 4, j = idx & 15;
        g_W1t[m * 16 + j] = W1[j * 64 + m] * 0.25f;
    }
}

__global__ void zero_acc_kernel(int n)
{
    int i = blockIdx.x * blockDim.x + threadIdx.x;
    if (i < n) g_acc[i] = 0.0;
}

__global__ void finish_kernel(float* __restrict__ out, int N)
{
    int i = blockIdx.x * blockDim.x + threadIdx.x;
    if (i < N * 32) {
        int c = i & 31;
        float v = (float)g_acc[i];
        out[i] = (c < 8) ? (v / (1.0f + __expf(-v))) : v;
    }
}

// ---------------- radial MLP + edge geometry precompute ----------------
__global__ void h_kernel(const float* __restrict__ pos, const int* __restrict__ ei, int E)
{
    __shared__ float sW1[W1_FLOATS];
    for (int i = threadIdx.x; i < W1_FLOATS; i += HTH) sW1[i] = g_W1t[i];
    __syncthreads();

    int e = blockIdx.x * HTH + threadIdx.x;
    if (e >= E) return;

    int r = ei[e];
    int c = ei[E + e];
    float evx = pos[3*r]   - pos[3*c];
    float evy = pos[3*r+1] - pos[3*c+1];
    float evz = pos[3*r+2] - pos[3*c+2];
    float d2  = evx*evx + evy*evy + evz*evz + 1e-12f;
    float d   = sqrtf(d2);
    float inv = 1.0f / d;
    g_n[e] = make_float4(evx*inv, evy*inv, evz*inv, 0.0f);

    float rb[16];
    #pragma unroll
    for (int j = 0; j < 16; j++) {
        float t = d - (float)j * (1.0f/3.0f);
        rb[j] = __expf(-4.5f * t * t);
    }

    #pragma unroll 1
    for (int ch = 0; ch < 8; ch++) {
        float hb[8];
        #pragma unroll
        for (int mm = 0; mm < 8; mm++) {
            const float4* wrow = (const float4*)(sW1 + (ch*8 + mm) * 16);
            float4 w0 = wrow[0], w1 = wrow[1], w2 = wrow[2], w3 = wrow[3];
            float acc0 = rb[0]*w0.x + rb[1]*w0.y + rb[2]*w0.z + rb[3]*w0.w;
            float acc1 = rb[4]*w1.x + rb[5]*w1.y + rb[6]*w1.z + rb[7]*w1.w;
            float acc2 = rb[8]*w2.x + rb[9]*w2.y + rb[10]*w2.z + rb[11]*w2.w;
            float acc3 = rb[12]*w3.x + rb[13]*w3.y + rb[14]*w3.z + rb[15]*w3.w;
            hb[mm] = fmaxf((acc0 + acc1) + (acc2 + acc3), 0.0f);
        }
        float4* dst = (float4*)(g_hp[ch] + (size_t)e * 8);
        dst[0] = make_float4(hb[0], hb[1], hb[2], hb[3]);
        dst[1] = make_float4(hb[4], hb[5], hb[6], hb[7]);
    }
}

// ---------------- main fused edge kernel: 2 edges / thread, no smem, 4 CTAs/SM ----------------
__global__ void __launch_bounds__(ETH, 4) edge_kernel(
    const float* __restrict__ x, const int* __restrict__ ei, int E)
{
    int gid = blockIdx.x * ETH + threadIdx.x;
    int e0 = 2 * gid;
    if (e0 >= E) return;
    int e1 = e0 + 1;
    bool v1 = (e1 < E);
    int e1c = v1 ? e1 : e0;

    int r0 = ei[e0];
    int r1 = ei[e1c];
    float4 n0 = g_n[e0];
    float4 n1 = g_n[e1c];

    const float4* xp0 = (const float4*)(x + (size_t)r0 * 32);
    const float4* xp1 = (const float4*)(x + (size_t)r1 * 32);

    // scalar channels + q = xv.n for both edges
    float pa0[8], qa0[8], pa1[8], qa1[8];
    {
        float4 a = xp0[0], b = xp0[1];
        pa0[0]=a.x; pa0[1]=a.y; pa0[2]=a.z; pa0[3]=a.w;
        pa0[4]=b.x; pa0[5]=b.y; pa0[6]=b.z; pa0[7]=b.w;
        float4 A=xp0[2], B=xp0[3], C=xp0[4], D=xp0[5], Ee=xp0[6], F=xp0[7];
        qa0[0] = A.x*n0.x + A.y*n0.y + A.z*n0.z;
        qa0[1] = A.w*n0.x + B.x*n0.y + B.y*n0.z;
        qa0[2] = B.z*n0.x + B.w*n0.y + C.x*n0.z;
        qa0[3] = C.y*n0.x + C.z*n0.y + C.w*n0.z;
        qa0[4] = D.x*n0.x + D.y*n0.y + D.z*n0.z;
        qa0[5] = D.w*n0.x + Ee.x*n0.y + Ee.y*n0.z;
        qa0[6] = Ee.z*n0.x + Ee.w*n0.y + F.x*n0.z;
        qa0[7] = F.y*n0.x + F.z*n0.y + F.w*n0.z;
    }
    {
        float4 a = xp1[0], b = xp1[1];
        pa1[0]=a.x; pa1[1]=a.y; pa1[2]=a.z; pa1[3]=a.w;
        pa1[4]=b.x; pa1[5]=b.y; pa1[6]=b.z; pa1[7]=b.w;
        float4 A=xp1[2], B=xp1[3], C=xp1[4], D=xp1[5], Ee=xp1[6], F=xp1[7];
        qa1[0] = A.x*n1.x + A.y*n1.y + A.z*n1.z;
        qa1[1] = A.w*n1.x + B.x*n1.y + B.y*n1.z;
        qa1[2] = B.z*n1.x + B.w*n1.y + C.x*n1.z;
        qa1[3] = C.y*n1.x + C.z*n1.y + C.w*n1.z;
        qa1[4] = D.x*n1.x + D.y*n1.y + D.z*n1.z;
        qa1[5] = D.w*n1.x + Ee.x*n1.y + Ee.y*n1.z;
        qa1[6] = Ee.z*n1.x + Ee.w*n1.y + F.x*n1.z;
        qa1[7] = F.y*n1.x + F.z*n1.y + F.w*n1.z;
    }

    // ===== phase 1: sections A,B,C,E (L1-resident LDG) -> outS + cn =====
    ull outS0[4]={0,0,0,0}, outS1[4]={0,0,0,0};
    ull cn0[4]={0,0,0,0},   cn1[4]={0,0,0,0};

    #pragma unroll 1
    for (int ch = 0; ch < 8; ch++) {
        const float4* h40 = (const float4*)(g_hp[ch] + (size_t)e0 * 8);
        const float4* h41 = (const float4*)(g_hp[ch] + (size_t)e1c * 8);
        float4 ha = __ldg(h40), hb = __ldg(h40 + 1);
        float4 hc = __ldg(h41), hd = __ldg(h41 + 1);
        ull hp0[8], hp1[8];
        hp0[0]=pk2(ha.x,ha.x); hp0[1]=pk2(ha.y,ha.y); hp0[2]=pk2(ha.z,ha.z); hp0[3]=pk2(ha.w,ha.w);
        hp0[4]=pk2(hb.x,hb.x); hp0[5]=pk2(hb.y,hb.y); hp0[6]=pk2(hb.z,hb.z); hp0[7]=pk2(hb.w,hb.w);
        hp1[0]=pk2(hc.x,hc.x); hp1[1]=pk2(hc.y,hc.y); hp1[2]=pk2(hc.z,hc.z); hp1[3]=pk2(hc.w,hc.w);
        hp1[4]=pk2(hd.x,hd.x); hp1[5]=pk2(hd.y,hd.y); hp1[6]=pk2(hd.z,hd.z); hp1[7]=pk2(hd.w,hd.w);

        const float* mb = g_M1 + ch * 8 * 256;

        #pragma unroll
        for (int u = 0; u < 8; u++) {
            ull pp0 = pk2(pa0[u], pa0[u]);
            ull qq0 = pk2(qa0[u], qa0[u]);
            ull pp1 = pk2(pa1[u], pa1[u]);
            ull qq1 = pk2(qa1[u], qa1[u]);
            #pragma unroll
            for (int sect = 0; sect < 4; sect++) {
                ull a0=0,a1=0,a2=0,a3=0, b0=0,b1=0,b2=0,b3=0;
                #pragma unroll
                for (int mm = 0; mm < 8; mm++) {
                    const float* rp = mb + mm * 256 + sect * 64 + u * 8;
                    ulonglong2 t0 = __ldg((const ulonglong2*)rp);
                    ulonglong2 t1 = __ldg((const ulonglong2*)(rp + 4));
                    a0 = fma2(t0.x, hp0[mm], a0); a1 = fma2(t0.y, hp0[mm], a1);
                    a2 = fma2(t1.x, hp0[mm], a2); a3 = fma2(t1.y, hp0[mm], a3);
                    b0 = fma2(t0.x, hp1[mm], b0); b1 = fma2(t0.y, hp1[mm], b1);
                    b2 = fma2(t1.x, hp1[mm], b2); b3 = fma2(t1.y, hp1[mm], b3);
                }
                ull c0 = (sect & 1) ? qq0 : pp0;
                ull c1 = (sect & 1) ? qq1 : pp1;
                if (sect < 2) {
                    outS0[0]=fma2(a0,c0,outS0[0]); outS0[1]=fma2(a1,c0,outS0[1]);
                    outS0[2]=fma2(a2,c0,outS0[2]); outS0[3]=fma2(a3,c0,outS0[3]);
                    outS1[0]=fma2(b0,c1,outS1[0]); outS1[1]=fma2(b1,c1,outS1[1]);
                    outS1[2]=fma2(b2,c1,outS1[2]); outS1[3]=fma2(b3,c1,outS1[3]);
                } else {
                    cn0[0]=fma2(a0,c0,cn0[0]); cn0[1]=fma2(a1,c0,cn0[1]);
                    cn0[2]=fma2(a2,c0,cn0[2]); cn0[3]=fma2(a3,c0,cn0[3]);
                    cn1[0]=fma2(b0,c1,cn1[0]); cn1[1]=fma2(b1,c1,cn1[1]);
                    cn1[2]=fma2(b2,c1,cn1[2]); cn1[3]=fma2(b3,c1,cn1[3]);
                }
            }
        }
    }

    // scalar-output atomics (frees outS registers before phase 2)
    {
        double* y0 = g_acc + (size_t)r0 * 32;
        #pragma unroll
        for (int wp = 0; wp < 4; wp++) {
            float2 s = upk(outS0[wp]);
            atomicAdd(y0 + wp*2,     (double)s.x);
            atomicAdd(y0 + wp*2 + 1, (double)s.y);
        }
        if (v1) {
            double* y1 = g_acc + (size_t)r1 * 32;
            #pragma unroll
            for (int wp = 0; wp < 4; wp++) {
                float2 s = upk(outS1[wp]);
                atomicAdd(y1 + wp*2,     (double)s.x);
                atomicAdd(y1 + wp*2 + 1, (double)s.y);
            }
        }
    }

    // ===== phase 2: section D' (L1-resident LDG) -> outV, seeded with cn ⊗ n =====
    ull oV0[3][4], oV1[3][4];
    {
        ull nn;
        nn = pk2(n0.x, n0.x);
        oV0[0][0]=mul2(cn0[0],nn); oV0[0][1]=mul2(cn0[1],nn); oV0[0][2]=mul2(cn0[2],nn); oV0[0][3]=mul2(cn0[3],nn);
        nn = pk2(n0.y, n0.y);
        oV0[1][0]=mul2(cn0[0],nn); oV0[1][1]=mul2(cn0[1],nn); oV0[1][2]=mul2(cn0[2],nn); oV0[1][3]=mul2(cn0[3],nn);
        nn = pk2(n0.z, n0.z);
        oV0[2][0]=mul2(cn0[0],nn); oV0[2][1]=mul2(cn0[1],nn); oV0[2][2]=mul2(cn0[2],nn); oV0[2][3]=mul2(cn0[3],nn);
        nn = pk2(n1.x, n1.x);
        oV1[0][0]=mul2(cn1[0],nn); oV1[0][1]=mul2(cn1[1],nn); oV1[0][2]=mul2(cn1[2],nn); oV1[0][3]=mul2(cn1[3],nn);
        nn = pk2(n1.y, n1.y);
        oV1[1][0]=mul2(cn1[0],nn); oV1[1][1]=mul2(cn1[1],nn); oV1[1][2]=mul2(cn1[2],nn); oV1[1][3]=mul2(cn1[3],nn);
        nn = pk2(n1.z, n1.z);
        oV1[2][0]=mul2(cn1[0],nn); oV1[2][1]=mul2(cn1[1],nn); oV1[2][2]=mul2(cn1[2],nn); oV1[2][3]=mul2(cn1[3],nn);
    }

    #pragma unroll 1
    for (int pass = 0; pass < 2; pass++) {
        float4 A0 = xp0[2 + pass*3], B0 = xp0[3 + pass*3], C0 = xp0[4 + pass*3];
        float4 A1 = xp1[2 + pass*3], B1 = xp1[3 + pass*3], C1 = xp1[4 + pass*3];
        float xv0[4][3], xv1[4][3];
        xv0[0][0]=A0.x; xv0[0][1]=A0.y; xv0[0][2]=A0.z;
        xv0[1][0]=A0.w; xv0[1][1]=B0.x; xv0[1][2]=B0.y;
        xv0[2][0]=B0.z; xv0[2][1]=B0.w; xv0[2][2]=C0.x;
        xv0[3][0]=C0.y; xv0[3][1]=C0.z; xv0[3][2]=C0.w;
        xv1[0][0]=A1.x; xv1[0][1]=A1.y; xv1[0][2]=A1.z;
        xv1[1][0]=A1.w; xv1[1][1]=B1.x; xv1[1][2]=B1.y;
        xv1[2][0]=B1.z; xv1[2][1]=B1.w; xv1[2][2]=C1.x;
        xv1[3][0]=C1.y; xv1[3][1]=C1.z; xv1[3][2]=C1.w;

        #pragma unroll 1
        for (int ch = 0; ch < 8; ch++) {
            const float4* h40 = (const float4*)(g_hp[ch] + (size_t)e0 * 8);
            const float4* h41 = (const float4*)(g_hp[ch] + (size_t)e1c * 8);
            float4 ha = __ldg(h40), hb = __ldg(h40 + 1);
            float4 hc = __ldg(h41), hd = __ldg(h41 + 1);
            ull hp0[8], hp1[8];
            hp0[0]=pk2(ha.x,ha.x); hp0[1]=pk2(ha.y,ha.y); hp0[2]=pk2(ha.z,ha.z); hp0[3]=pk2(ha.w,ha.w);
            hp0[4]=pk2(hb.x,hb.x); hp0[5]=pk2(hb.y,hb.y); hp0[6]=pk2(hb.z,hb.z); hp0[7]=pk2(hb.w,hb.w);
            hp1[0]=pk2(hc.x,hc.x); hp1[1]=pk2(hc.y,hc.y); hp1[2]=pk2(hc.z,hc.z); hp1[3]=pk2(hc.w,hc.w);
            hp1[4]=pk2(hd.x,hd.x); hp1[5]=pk2(hd.y,hd.y); hp1[6]=pk2(hd.z,hd.z); hp1[7]=pk2(hd.w,hd.w);

            const float* mb = g_M2 + ch * 8 * 64 + pass * 32;

            #pragma unroll
            for (int u = 0; u < 4; u++) {
                ull a0=0,a1=0,a2=0,a3=0, b0=0,b1=0,b2=0,b3=0;
                #pragma unroll
                for (int mm = 0; mm < 8; mm++) {
                    const float* rp = mb + mm * 64 + u * 8;
                    ulonglong2 t0 = __ldg((const ulonglong2*)rp);
                    ulonglong2 t1 = __ldg((const ulonglong2*)(rp + 4));
                    a0 = fma2(t0.x, hp0[mm], a0); a1 = fma2(t0.y, hp0[mm], a1);
                    a2 = fma2(t1.x, hp0[mm], a2); a3 = fma2(t1.y, hp0[mm], a3);
                    b0 = fma2(t0.x, hp1[mm], b0); b1 = fma2(t0.y, hp1[mm], b1);
                    b2 = fma2(t1.x, hp1[mm], b2); b3 = fma2(t1.y, hp1[mm], b3);
                }
                #pragma unroll
                for (int k = 0; k < 3; k++) {
                    ull x0 = pk2(xv0[u][k], xv0[u][k]);
                    ull x1 = pk2(xv1[u][k], xv1[u][k]);
                    oV0[k][0]=fma2(a0,x0,oV0[k][0]); oV0[k][1]=fma2(a1,x0,oV0[k][1]);
                    oV0[k][2]=fma2(a2,x0,oV0[k][2]); oV0[k][3]=fma2(a3,x0,oV0[k][3]);
                    oV1[k][0]=fma2(b0,x1,oV1[k][0]); oV1[k][1]=fma2(b1,x1,oV1[k][1]);
                    oV1[k][2]=fma2(b2,x1,oV1[k][2]); oV1[k][3]=fma2(b3,x1,oV1[k][3]);
                }
            }
        }
    }

    // vector-output atomics
    {
        double* y0 = g_acc + (size_t)r0 * 32;
        #pragma unroll
        for (int wp = 0; wp < 4; wp++) {
            #pragma unroll
            for (int k = 0; k < 3; k++) {
                float2 v = upk(oV0[k][wp]);
                atomicAdd(y0 + 8 + (wp*2)*3   + k, (double)v.x);
                atomicAdd(y0 + 8 + (wp*2+1)*3 + k, (double)v.y);
            }
        }
        if (v1) {
            double* y1 = g_acc + (size_t)r1 * 32;
            #pragma unroll
            for (int wp = 0; wp < 4; wp++) {
                #pragma unroll
                for (int k = 0; k < 3; k++) {
                    float2 v = upk(oV1[k][wp]);
                    atomicAdd(y1 + 8 + (wp*2)*3   + k, (double)v.x);
                    atomicAdd(y1 + 8 + (wp*2+1)*3 + k, (double)v.y);
                }
            }
        }
    }
}

extern "C" void kernel_launch(void* const* d_in, const int* in_sizes, int n_in,
                              void* d_out, int out_size)
{
    const float* x   = (const float*)d_in[0];
    const float* pos = (const float*)d_in[1];
    const int*   ei  = (const int*)d_in[2];
    const float* W1  = (const float*)d_in[3];
    const float* W2  = (const float*)d_in[4];
    float* out = (float*)d_out;

    int E = in_sizes[2] / 2;
    int N = in_sizes[1] / 3;

    prep_kernel<<<(M_FLOATS + 255) / 256, 256>>>(W1, W2);
    zero_acc_kernel<<<(N * 32 + 255) / 256, 256>>>(N * 32);
    h_kernel<<<(E + HTH - 1) / HTH, HTH>>>(pos, ei, E);

    int pairs = (E + 1) / 2;
    int blocks = (pairs + ETH - 1) / ETH;
    edge_kernel<<<blocks, ETH>>>(x, ei, E);

    finish_kernel<<<(N * 32 + 255) / 256, 256>>>(out, N);
}

// round 7
// speedup vs baseline: 1.3265x; 1.3265x over previous
#include <cuda_runtime.h>

typedef unsigned long long ull;

#define ETH 128
#define HTH 256
#define M_FLOATS (64*320)
#define M1_FLOATS (64*256)
#define M2_FLOATS (64*64)
#define W1_FLOATS (64*16)
#define N_NODES 25000
#define E_MAX 400000

__device__ float  g_M1[M1_FLOATS];            // [m][sect4:{A,B,C,E}][u][w]  (smem-staged)
__device__ float  g_M2[M2_FLOATS];            // [m][u][w]  D' = D - E/3    (L1-resident LDG)
__device__ float  g_W1t[W1_FLOATS];           // [m][16] W1^T / 4
__device__ double g_acc[N_NODES * 32];        // segment-sum accumulator
__device__ float4 g_hp4[8][2][E_MAX];         // [chunk][half][e] radial MLP outputs (coalesced)
__device__ float4 g_n[E_MAX];                 // unit edge vectors

__device__ __forceinline__ ull pk2(float a, float b){ ull r; asm("mov.b64 %0, {%1,%2};" : "=l"(r) : "f"(a), "f"(b)); return r; }
__device__ __forceinline__ ull fma2(ull a, ull b, ull c){ ull d; asm("fma.rn.f32x2 %0, %1, %2, %3;" : "=l"(d) : "l"(a), "l"(b), "l"(c)); return d; }
__device__ __forceinline__ ull mul2(ull a, ull b){ ull d; asm("mul.rn.f32x2 %0, %1, %2;" : "=l"(d) : "l"(a), "l"(b)); return d; }
__device__ __forceinline__ float2 upk(ull a){ float2 f; asm("mov.b64 {%0,%1}, %2;" : "=f"(f.x), "=f"(f.y) : "l"(a)); return f; }

// ---------------- prep: fold W2 + scales into M1/M2 ----------------
__global__ void prep_kernel(const float* __restrict__ W1, const float* __restrict__ W2)
{
    int idx = blockIdx.x * blockDim.x + threadIdx.x;
    const float a0  = 0.17677669529663687f;   // 1/sqrt(32)
    const float a1  = 0.27386127875258304f;   // sqrt(3/40)
    const float a1s = 0.15811388300841897f;   // a1/sqrt(3)
    const float aE  = 0.33541019662496846f;   // a1*sqrt(1.5)
    if (idx < M_FLOATS) {
        int m = idx / 320, o = idx % 320;
        int sect = o >> 6, r = o & 63, u = r >> 3, w = r & 7;
        const float* Vm = W2 + m * 576;
        float eval = aE * 0.125f * Vm[512 + u * 8 + w];
        float val;
        if (sect < 4) {
            int t0 = sect * 128 + u * 16 + w;
            float s = (sect <= 1) ? a0 : (sect == 2 ? a1 : a1s);
            val = s * 0.125f * (Vm[t0] + Vm[t0 + 8]);
            if (sect == 3) val -= eval * (1.0f / 3.0f);   // fold -E/3 into D
        } else {
            val = eval;
        }
        if (sect == 3) {
            g_M2[m * 64 + u * 8 + w] = val;
        } else {
            int s4 = (sect == 4) ? 3 : sect;   // {A,B,C,E}
            g_M1[m * 256 + s4 * 64 + u * 8 + w] = val;
        }
    }
    if (idx < W1_FLOATS) {
        int m = idx >> 4, j = idx & 15;
        g_W1t[m * 16 + j] = W1[j * 64 + m] * 0.25f;
    }
}

__global__ void zero_acc_kernel(int n)
{
    int i = blockIdx.x * blockDim.x + threadIdx.x;
    if (i < n) g_acc[i] = 0.0;
}

__global__ void finish_kernel(float* __restrict__ out, int N)
{
    int i = blockIdx.x * blockDim.x + threadIdx.x;
    if (i < N * 32) {
        int c = i & 31;
        float v = (float)g_acc[i];
        out[i] = (c < 8) ? (v / (1.0f + __expf(-v))) : v;
    }
}

// ---------------- radial MLP + edge geometry precompute ----------------
__global__ void h_kernel(const float* __restrict__ pos, const int* __restrict__ ei, int E)
{
    __shared__ float sW1[W1_FLOATS];
    for (int i = threadIdx.x; i < W1_FLOATS; i += HTH) sW1[i] = g_W1t[i];
    __syncthreads();

    int e = blockIdx.x * HTH + threadIdx.x;
    if (e >= E) return;

    int r = ei[e];
    int c = ei[E + e];
    float evx = pos[3*r]   - pos[3*c];
    float evy = pos[3*r+1] - pos[3*c+1];
    float evz = pos[3*r+2] - pos[3*c+2];
    float d2  = evx*evx + evy*evy + evz*evz + 1e-12f;
    float d   = sqrtf(d2);
    float inv = 1.0f / d;
    g_n[e] = make_float4(evx*inv, evy*inv, evz*inv, 0.0f);

    float rb[16];
    #pragma unroll
    for (int j = 0; j < 16; j++) {
        float t = d - (float)j * (1.0f/3.0f);
        rb[j] = __expf(-4.5f * t * t);
    }

    #pragma unroll 1
    for (int ch = 0; ch < 8; ch++) {
        float hb[8];
        #pragma unroll
        for (int mm = 0; mm < 8; mm++) {
            const float4* wrow = (const float4*)(sW1 + (ch*8 + mm) * 16);
            float4 w0 = wrow[0], w1 = wrow[1], w2 = wrow[2], w3 = wrow[3];
            float acc0 = rb[0]*w0.x + rb[1]*w0.y + rb[2]*w0.z + rb[3]*w0.w;
            float acc1 = rb[4]*w1.x + rb[5]*w1.y + rb[6]*w1.z + rb[7]*w1.w;
            float acc2 = rb[8]*w2.x + rb[9]*w2.y + rb[10]*w2.z + rb[11]*w2.w;
            float acc3 = rb[12]*w3.x + rb[13]*w3.y + rb[14]*w3.z + rb[15]*w3.w;
            hb[mm] = fmaxf((acc0 + acc1) + (acc2 + acc3), 0.0f);
        }
        g_hp4[ch][0][e] = make_float4(hb[0], hb[1], hb[2], hb[3]);
        g_hp4[ch][1][e] = make_float4(hb[4], hb[5], hb[6], hb[7]);
    }
}

// ---------------- main fused edge kernel: 2 blocked edges / thread, 3 CTAs/SM ----------------
__global__ void __launch_bounds__(ETH, 3) edge_kernel(
    const float* __restrict__ x, const int* __restrict__ ei, int E, int H)
{
    extern __shared__ float smM1[];   // 16384 floats = 64 KB (M1 only)
    #pragma unroll 1
    for (int i = threadIdx.x; i < M1_FLOATS; i += ETH) smM1[i] = g_M1[i];
    __syncthreads();

    int gid = blockIdx.x * ETH + threadIdx.x;
    if (gid >= H) return;
    int e0 = gid;                 // blocked split: lane-consecutive -> coalesced
    int e1 = gid + H;
    bool v1 = (e1 < E);
    int e1c = v1 ? e1 : e0;

    int r0 = ei[e0];
    int r1 = ei[e1c];
    float4 n0 = g_n[e0];
    float4 n1 = g_n[e1c];

    const float4* xp0 = (const float4*)(x + (size_t)r0 * 32);
    const float4* xp1 = (const float4*)(x + (size_t)r1 * 32);

    // scalar channels + q = xv.n for both edges
    float pa0[8], qa0[8], pa1[8], qa1[8];
    {
        float4 a = xp0[0], b = xp0[1];
        pa0[0]=a.x; pa0[1]=a.y; pa0[2]=a.z; pa0[3]=a.w;
        pa0[4]=b.x; pa0[5]=b.y; pa0[6]=b.z; pa0[7]=b.w;
        float4 A=xp0[2], B=xp0[3], C=xp0[4], D=xp0[5], Ee=xp0[6], F=xp0[7];
        qa0[0] = A.x*n0.x + A.y*n0.y + A.z*n0.z;
        qa0[1] = A.w*n0.x + B.x*n0.y + B.y*n0.z;
        qa0[2] = B.z*n0.x + B.w*n0.y + C.x*n0.z;
        qa0[3] = C.y*n0.x + C.z*n0.y + C.w*n0.z;
        qa0[4] = D.x*n0.x + D.y*n0.y + D.z*n0.z;
        qa0[5] = D.w*n0.x + Ee.x*n0.y + Ee.y*n0.z;
        qa0[6] = Ee.z*n0.x + Ee.w*n0.y + F.x*n0.z;
        qa0[7] = F.y*n0.x + F.z*n0.y + F.w*n0.z;
    }
    {
        float4 a = xp1[0], b = xp1[1];
        pa1[0]=a.x; pa1[1]=a.y; pa1[2]=a.z; pa1[3]=a.w;
        pa1[4]=b.x; pa1[5]=b.y; pa1[6]=b.z; pa1[7]=b.w;
        float4 A=xp1[2], B=xp1[3], C=xp1[4], D=xp1[5], Ee=xp1[6], F=xp1[7];
        qa1[0] = A.x*n1.x + A.y*n1.y + A.z*n1.z;
        qa1[1] = A.w*n1.x + B.x*n1.y + B.y*n1.z;
        qa1[2] = B.z*n1.x + B.w*n1.y + C.x*n1.z;
        qa1[3] = C.y*n1.x + C.z*n1.y + C.w*n1.z;
        qa1[4] = D.x*n1.x + D.y*n1.y + D.z*n1.z;
        qa1[5] = D.w*n1.x + Ee.x*n1.y + Ee.y*n1.z;
        qa1[6] = Ee.z*n1.x + Ee.w*n1.y + F.x*n1.z;
        qa1[7] = F.y*n1.x + F.z*n1.y + F.w*n1.z;
    }

    // ===== phase 1: sections A,B,C,E (smem) -> outS + cn =====
    ull outS0[4]={0,0,0,0}, outS1[4]={0,0,0,0};
    ull cn0[4]={0,0,0,0},   cn1[4]={0,0,0,0};

    #pragma unroll 1
    for (int ch = 0; ch < 8; ch++) {
        float4 ha = __ldg(&g_hp4[ch][0][e0]);
        float4 hb = __ldg(&g_hp4[ch][1][e0]);
        float4 hc = __ldg(&g_hp4[ch][0][e1c]);
        float4 hd = __ldg(&g_hp4[ch][1][e1c]);
        ull hp0[8], hp1[8];
        hp0[0]=pk2(ha.x,ha.x); hp0[1]=pk2(ha.y,ha.y); hp0[2]=pk2(ha.z,ha.z); hp0[3]=pk2(ha.w,ha.w);
        hp0[4]=pk2(hb.x,hb.x); hp0[5]=pk2(hb.y,hb.y); hp0[6]=pk2(hb.z,hb.z); hp0[7]=pk2(hb.w,hb.w);
        hp1[0]=pk2(hc.x,hc.x); hp1[1]=pk2(hc.y,hc.y); hp1[2]=pk2(hc.z,hc.z); hp1[3]=pk2(hc.w,hc.w);
        hp1[4]=pk2(hd.x,hd.x); hp1[5]=pk2(hd.y,hd.y); hp1[6]=pk2(hd.z,hd.z); hp1[7]=pk2(hd.w,hd.w);

        const float* mb = smM1 + ch * 8 * 256;

        #pragma unroll
        for (int u = 0; u < 8; u++) {
            ull pp0 = pk2(pa0[u], pa0[u]);
            ull qq0 = pk2(qa0[u], qa0[u]);
            ull pp1 = pk2(pa1[u], pa1[u]);
            ull qq1 = pk2(qa1[u], qa1[u]);
            #pragma unroll
            for (int sect = 0; sect < 4; sect++) {
                ull a0=0,a1=0,a2=0,a3=0, b0=0,b1=0,b2=0,b3=0;
                #pragma unroll
                for (int mm = 0; mm < 8; mm++) {
                    const float* rp = mb + mm * 256 + sect * 64 + u * 8;
                    ulonglong2 t0 = *(const ulonglong2*)rp;
                    ulonglong2 t1 = *(const ulonglong2*)(rp + 4);
                    a0 = fma2(t0.x, hp0[mm], a0); a1 = fma2(t0.y, hp0[mm], a1);
                    a2 = fma2(t1.x, hp0[mm], a2); a3 = fma2(t1.y, hp0[mm], a3);
                    b0 = fma2(t0.x, hp1[mm], b0); b1 = fma2(t0.y, hp1[mm], b1);
                    b2 = fma2(t1.x, hp1[mm], b2); b3 = fma2(t1.y, hp1[mm], b3);
                }
                ull c0 = (sect & 1) ? qq0 : pp0;
                ull c1 = (sect & 1) ? qq1 : pp1;
                if (sect < 2) {
                    outS0[0]=fma2(a0,c0,outS0[0]); outS0[1]=fma2(a1,c0,outS0[1]);
                    outS0[2]=fma2(a2,c0,outS0[2]); outS0[3]=fma2(a3,c0,outS0[3]);
                    outS1[0]=fma2(b0,c1,outS1[0]); outS1[1]=fma2(b1,c1,outS1[1]);
                    outS1[2]=fma2(b2,c1,outS1[2]); outS1[3]=fma2(b3,c1,outS1[3]);
                } else {
                    cn0[0]=fma2(a0,c0,cn0[0]); cn0[1]=fma2(a1,c0,cn0[1]);
                    cn0[2]=fma2(a2,c0,cn0[2]); cn0[3]=fma2(a3,c0,cn0[3]);
                    cn1[0]=fma2(b0,c1,cn1[0]); cn1[1]=fma2(b1,c1,cn1[1]);
                    cn1[2]=fma2(b2,c1,cn1[2]); cn1[3]=fma2(b3,c1,cn1[3]);
                }
            }
        }
    }

    // scalar-output atomics (frees outS registers before phase 2)
    {
        double* y0 = g_acc + (size_t)r0 * 32;
        #pragma unroll
        for (int wp = 0; wp < 4; wp++) {
            float2 s = upk(outS0[wp]);
            atomicAdd(y0 + wp*2,     (double)s.x);
            atomicAdd(y0 + wp*2 + 1, (double)s.y);
        }
        if (v1) {
            double* y1 = g_acc + (size_t)r1 * 32;
            #pragma unroll
            for (int wp = 0; wp < 4; wp++) {
                float2 s = upk(outS1[wp]);
                atomicAdd(y1 + wp*2,     (double)s.x);
                atomicAdd(y1 + wp*2 + 1, (double)s.y);
            }
        }
    }

    // ===== phase 2: section D' (gmem/L1) -> outV, seeded with cn ⊗ n =====
    ull oV0[3][4], oV1[3][4];
    {
        ull nn;
        nn = pk2(n0.x, n0.x);
        oV0[0][0]=mul2(cn0[0],nn); oV0[0][1]=mul2(cn0[1],nn); oV0[0][2]=mul2(cn0[2],nn); oV0[0][3]=mul2(cn0[3],nn);
        nn = pk2(n0.y, n0.y);
        oV0[1][0]=mul2(cn0[0],nn); oV0[1][1]=mul2(cn0[1],nn); oV0[1][2]=mul2(cn0[2],nn); oV0[1][3]=mul2(cn0[3],nn);
        nn = pk2(n0.z, n0.z);
        oV0[2][0]=mul2(cn0[0],nn); oV0[2][1]=mul2(cn0[1],nn); oV0[2][2]=mul2(cn0[2],nn); oV0[2][3]=mul2(cn0[3],nn);
        nn = pk2(n1.x, n1.x);
        oV1[0][0]=mul2(cn1[0],nn); oV1[0][1]=mul2(cn1[1],nn); oV1[0][2]=mul2(cn1[2],nn); oV1[0][3]=mul2(cn1[3],nn);
        nn = pk2(n1.y, n1.y);
        oV1[1][0]=mul2(cn1[0],nn); oV1[1][1]=mul2(cn1[1],nn); oV1[1][2]=mul2(cn1[2],nn); oV1[1][3]=mul2(cn1[3],nn);
        nn = pk2(n1.z, n1.z);
        oV1[2][0]=mul2(cn1[0],nn); oV1[2][1]=mul2(cn1[1],nn); oV1[2][2]=mul2(cn1[2],nn); oV1[2][3]=mul2(cn1[3],nn);
    }

    #pragma unroll 1
    for (int pass = 0; pass < 2; pass++) {
        float4 A0 = xp0[2 + pass*3], B0 = xp0[3 + pass*3], C0 = xp0[4 + pass*3];
        float4 A1 = xp1[2 + pass*3], B1 = xp1[3 + pass*3], C1 = xp1[4 + pass*3];
        float xv0[4][3], xv1[4][3];
        xv0[0][0]=A0.x; xv0[0][1]=A0.y; xv0[0][2]=A0.z;
        xv0[1][0]=A0.w; xv0[1][1]=B0.x; xv0[1][2]=B0.y;
        xv0[2][0]=B0.z; xv0[2][1]=B0.w; xv0[2][2]=C0.x;
        xv0[3][0]=C0.y; xv0[3][1]=C0.z; xv0[3][2]=C0.w;
        xv1[0][0]=A1.x; xv1[0][1]=A1.y; xv1[0][2]=A1.z;
        xv1[1][0]=A1.w; xv1[1][1]=B1.x; xv1[1][2]=B1.y;
        xv1[2][0]=B1.z; xv1[2][1]=B1.w; xv1[2][2]=C1.x;
        xv1[3][0]=C1.y; xv1[3][1]=C1.z; xv1[3][2]=C1.w;

        #pragma unroll 1
        for (int ch = 0; ch < 8; ch++) {
            float4 ha = __ldg(&g_hp4[ch][0][e0]);
            float4 hb = __ldg(&g_hp4[ch][1][e0]);
            float4 hc = __ldg(&g_hp4[ch][0][e1c]);
            float4 hd = __ldg(&g_hp4[ch][1][e1c]);
            ull hp0[8], hp1[8];
            hp0[0]=pk2(ha.x,ha.x); hp0[1]=pk2(ha.y,ha.y); hp0[2]=pk2(ha.z,ha.z); hp0[3]=pk2(ha.w,ha.w);
            hp0[4]=pk2(hb.x,hb.x); hp0[5]=pk2(hb.y,hb.y); hp0[6]=pk2(hb.z,hb.z); hp0[7]=pk2(hb.w,hb.w);
            hp1[0]=pk2(hc.x,hc.x); hp1[1]=pk2(hc.y,hc.y); hp1[2]=pk2(hc.z,hc.z); hp1[3]=pk2(hc.w,hc.w);
            hp1[4]=pk2(hd.x,hd.x); hp1[5]=pk2(hd.y,hd.y); hp1[6]=pk2(hd.z,hd.z); hp1[7]=pk2(hd.w,hd.w);

            const float* mb = g_M2 + ch * 8 * 64 + pass * 32;

            #pragma unroll
            for (int u = 0; u < 4; u++) {
                ull a0=0,a1=0,a2=0,a3=0, b0=0,b1=0,b2=0,b3=0;
                #pragma unroll
                for (int mm = 0; mm < 8; mm++) {
                    const float* rp = mb + mm * 64 + u * 8;
                    ulonglong2 t0 = __ldg((const ulonglong2*)rp);
                    ulonglong2 t1 = __ldg((const ulonglong2*)(rp + 4));
                    a0 = fma2(t0.x, hp0[mm], a0); a1 = fma2(t0.y, hp0[mm], a1);
                    a2 = fma2(t1.x, hp0[mm], a2); a3 = fma2(t1.y, hp0[mm], a3);
                    b0 = fma2(t0.x, hp1[mm], b0); b1 = fma2(t0.y, hp1[mm], b1);
                    b2 = fma2(t1.x, hp1[mm], b2); b3 = fma2(t1.y, hp1[mm], b3);
                }
                #pragma unroll
                for (int k = 0; k < 3; k++) {
                    ull x0 = pk2(xv0[u][k], xv0[u][k]);
                    ull x1 = pk2(xv1[u][k], xv1[u][k]);
                    oV0[k][0]=fma2(a0,x0,oV0[k][0]); oV0[k][1]=fma2(a1,x0,oV0[k][1]);
                    oV0[k][2]=fma2(a2,x0,oV0[k][2]); oV0[k][3]=fma2(a3,x0,oV0[k][3]);
                    oV1[k][0]=fma2(b0,x1,oV1[k][0]); oV1[k][1]=fma2(b1,x1,oV1[k][1]);
                    oV1[k][2]=fma2(b2,x1,oV1[k][2]); oV1[k][3]=fma2(b3,x1,oV1[k][3]);
                }
            }
        }
    }

    // vector-output atomics
    {
        double* y0 = g_acc + (size_t)r0 * 32;
        #pragma unroll
        for (int wp = 0; wp < 4; wp++) {
            #pragma unroll
            for (int k = 0; k < 3; k++) {
                float2 v = upk(oV0[k][wp]);
                atomicAdd(y0 + 8 + (wp*2)*3   + k, (double)v.x);
                atomicAdd(y0 + 8 + (wp*2+1)*3 + k, (double)v.y);
            }
        }
        if (v1) {
            double* y1 = g_acc + (size_t)r1 * 32;
            #pragma unroll
            for (int wp = 0; wp < 4; wp++) {
                #pragma unroll
                for (int k = 0; k < 3; k++) {
                    float2 v = upk(oV1[k][wp]);
                    atomicAdd(y1 + 8 + (wp*2)*3   + k, (double)v.x);
                    atomicAdd(y1 + 8 + (wp*2+1)*3 + k, (double)v.y);
                }
            }
        }
    }
}

extern "C" void kernel_launch(void* const* d_in, const int* in_sizes, int n_in,
                              void* d_out, int out_size)
{
    const float* x   = (const float*)d_in[0];
    const float* pos = (const float*)d_in[1];
    const int*   ei  = (const int*)d_in[2];
    const float* W1  = (const float*)d_in[3];
    const float* W2  = (const float*)d_in[4];
    float* out = (float*)d_out;

    int E = in_sizes[2] / 2;
    int N = in_sizes[1] / 3;
    int H = (E + 1) / 2;

    prep_kernel<<<(M_FLOATS + 255) / 256, 256>>>(W1, W2);
    zero_acc_kernel<<<(N * 32 + 255) / 256, 256>>>(N * 32);
    h_kernel<<<(E + HTH - 1) / HTH, HTH>>>(pos, ei, E);

    int blocks = (H + ETH - 1) / ETH;
    size_t smem = M1_FLOATS * sizeof(float);
    cudaFuncSetAttribute(edge_kernel, cudaFuncAttributeMaxDynamicSharedMemorySize, (int)smem);
    edge_kernel<<<blocks, ETH, smem>>>(x, ei, E, H);

    finish_kernel<<<(N * 32 + 255) / 256, 256>>>(out, N);
}

// round 9
// speedup vs baseline: 1.6192x; 1.2207x over previous
#include <cuda_runtime.h>

typedef unsigned long long ull;

#define GT 128
#define HTH 256
#define M_FLOATS (64*320)
#define MS_FLOATS (5*64*64)
#define W1_FLOATS (64*16)
#define N_NODES 25000
#define E_MAX 400000

__device__ float  g_Ms[MS_FLOATS];            // [s][m][o=u*8+w] folded weights, section-major
__device__ float  g_W1t[W1_FLOATS];           // [m][16] W1^T / 4
__device__ double g_acc[N_NODES * 32];        // segment-sum accumulator
__device__ float  g_hT[64 * (size_t)E_MAX];   // [m][e] radial MLP outputs, k-major
__device__ float4 g_n[E_MAX];                 // unit edge vectors

__device__ __forceinline__ ull pk2(float a, float b){ ull r; asm("mov.b64 %0, {%1,%2};" : "=l"(r) : "f"(a), "f"(b)); return r; }
__device__ __forceinline__ ull fma2(ull a, ull b, ull c){ ull d; asm("fma.rn.f32x2 %0, %1, %2, %3;" : "=l"(d) : "l"(a), "l"(b), "l"(c)); return d; }
__device__ __forceinline__ ull mul2(ull a, ull b){ ull d; asm("mul.rn.f32x2 %0, %1, %2;" : "=l"(d) : "l"(a), "l"(b)); return d; }
__device__ __forceinline__ float2 upk(ull a){ float2 f; asm("mov.b64 {%0,%1}, %2;" : "=f"(f.x), "=f"(f.y) : "l"(a)); return f; }

// ---------------- prep: fold W2 + scales into g_Ms[5][64][64] ----------------
__global__ void prep_kernel(const float* __restrict__ W1, const float* __restrict__ W2)
{
    int idx = blockIdx.x * blockDim.x + threadIdx.x;
    const float a0  = 0.17677669529663687f;   // 1/sqrt(32)
    const float a1  = 0.27386127875258304f;   // sqrt(3/40)
    const float a1s = 0.15811388300841897f;   // a1/sqrt(3)
    const float aE  = 0.33541019662496846f;   // a1*sqrt(1.5)
    if (idx < M_FLOATS) {
        int m = idx / 320, o = idx % 320;
        int sect = o >> 6, r = o & 63, u = r >> 3, w = r & 7;
        const float* Vm = W2 + m * 576;
        float eval = aE * 0.125f * Vm[512 + u * 8 + w];
        float val; int s;
        if (sect < 4) {
            int t0 = sect * 128 + u * 16 + w;
            float sc = (sect <= 1) ? a0 : (sect == 2 ? a1 : a1s);
            val = sc * 0.125f * (Vm[t0] + Vm[t0 + 8]);
            if (sect == 3) { val -= eval * (1.0f/3.0f); s = 4; }  // D' -> slot 4
            else s = sect;                                        // A,B,C -> 0,1,2
        } else {
            val = eval; s = 3;                                    // E -> slot 3
        }
        g_Ms[s * 4096 + m * 64 + r] = val;
    }
    if (idx < W1_FLOATS) {
        int m = idx >> 4, j = idx & 15;
        g_W1t[m * 16 + j] = W1[j * 64 + m] * 0.25f;
    }
}

__global__ void zero_acc_kernel(int n)
{
    int i = blockIdx.x * blockDim.x + threadIdx.x;
    if (i < n) g_acc[i] = 0.0;
}

__global__ void finish_kernel(float* __restrict__ out, int N)
{
    int i = blockIdx.x * blockDim.x + threadIdx.x;
    if (i < N * 32) {
        int c = i & 31;
        float v = (float)g_acc[i];
        out[i] = (c < 8) ? (v / (1.0f + __expf(-v))) : v;
    }
}

// ---------------- radial MLP + edge geometry precompute (k-major h) ----------------
__global__ void h_kernel(const float* __restrict__ pos, const int* __restrict__ ei, int E)
{
    __shared__ float sW1[W1_FLOATS];
    for (int i = threadIdx.x; i < W1_FLOATS; i += HTH) sW1[i] = g_W1t[i];
    __syncthreads();

    int e = blockIdx.x * HTH + threadIdx.x;
    if (e >= E) return;

    int r = ei[e];
    int c = ei[E + e];
    float evx = pos[3*r]   - pos[3*c];
    float evy = pos[3*r+1] - pos[3*c+1];
    float evz = pos[3*r+2] - pos[3*c+2];
    float d2  = evx*evx + evy*evy + evz*evz + 1e-12f;
    float d   = sqrtf(d2);
    float inv = 1.0f / d;
    g_n[e] = make_float4(evx*inv, evy*inv, evz*inv, 0.0f);

    float rb[16];
    #pragma unroll
    for (int j = 0; j < 16; j++) {
        float t = d - (float)j * (1.0f/3.0f);
        rb[j] = __expf(-4.5f * t * t);
    }

    #pragma unroll 1
    for (int m = 0; m < 64; m++) {
        const float4* wrow = (const float4*)(sW1 + m * 16);
        float4 w0 = wrow[0], w1 = wrow[1], w2 = wrow[2], w3 = wrow[3];
        float acc0 = rb[0]*w0.x + rb[1]*w0.y + rb[2]*w0.z + rb[3]*w0.w;
        float acc1 = rb[4]*w1.x + rb[5]*w1.y + rb[6]*w1.z + rb[7]*w1.w;
        float acc2 = rb[8]*w2.x + rb[9]*w2.y + rb[10]*w2.z + rb[11]*w2.w;
        float acc3 = rb[12]*w3.x + rb[13]*w3.y + rb[14]*w3.z + rb[15]*w3.w;
        g_hT[(size_t)m * E_MAX + e] = fmaxf((acc0 + acc1) + (acc2 + acc3), 0.0f);
    }
}

// ---------------- fused tile kernel: GEMM (128e x 64o, K=64) + per-edge epilogue ----------------
// smem: sh_h[64][128] (32KB) | sh_M[64][64] (16KB) | sh_C[128][68] (34KB)
// C row stride 68 floats = 272B = 17*16B  -> every 16B access stays aligned
#define SH_H 0
#define SH_M 8192
#define SH_C 12288
#define C_STRIDE 68
#define SM_TOTAL ((12288 + 128*C_STRIDE) * 4)

__global__ void __launch_bounds__(GT, 2) edge_kernel(
    const float* __restrict__ x, const int* __restrict__ ei, int E)
{
    extern __shared__ float sm[];
    int tid = threadIdx.x;
    int e_base = blockIdx.x * 128;

    // load h tile [64][128] (coalesced float4)
    {
        float4* dst = (float4*)(sm + SH_H);
        int c0 = e_base >> 2;
        #pragma unroll
        for (int it = 0; it < 16; it++) {
            int i = tid + it * 128;
            int m = i >> 5, c = i & 31;
            dst[i] = __ldg((const float4*)(g_hT + (size_t)m * E_MAX) + c0 + c);
        }
    }

    // per-thread edge data (epilogue edge = e_base + tid)
    int e = e_base + tid;
    bool ve = (e < E);
    int ec = ve ? e : 0;
    int r = ei[ec];
    float4 nf = g_n[ec];
    const float4* xp = (const float4*)(x + (size_t)r * 32);

    float p[8], q[8];
    {
        float4 a = xp[0], b = xp[1];
        p[0]=a.x; p[1]=a.y; p[2]=a.z; p[3]=a.w;
        p[4]=b.x; p[5]=b.y; p[6]=b.z; p[7]=b.w;
        float4 A=xp[2], B=xp[3], C=xp[4], D=xp[5], Ee=xp[6], F=xp[7];
        q[0] = A.x*nf.x + A.y*nf.y + A.z*nf.z;
        q[1] = A.w*nf.x + B.x*nf.y + B.y*nf.z;
        q[2] = B.z*nf.x + B.w*nf.y + C.x*nf.z;
        q[3] = C.y*nf.x + C.z*nf.y + C.w*nf.z;
        q[4] = D.x*nf.x + D.y*nf.y + D.z*nf.z;
        q[5] = D.w*nf.x + Ee.x*nf.y + Ee.y*nf.z;
        q[6] = Ee.z*nf.x + Ee.w*nf.y + F.x*nf.z;
        q[7] = F.y*nf.x + F.z*nf.y + F.w*nf.z;
    }

    int eg = tid >> 3, og = tid & 7;
    const float* hB = sm + SH_H + eg * 8;
    const float* mB = sm + SH_M + og * 8;

    ull outS[4] = {0,0,0,0};
    ull cn[4]   = {0,0,0,0};
    ull oV[3][4] = {{0,0,0,0},{0,0,0,0},{0,0,0,0}};

    #pragma unroll 1
    for (int s = 0; s < 5; s++) {
        __syncthreads();   // protect sh_M / sh_C reuse
        // fill M section [64][64]
        {
            const float4* Mg = (const float4*)(g_Ms + s * 4096);
            float4* dstM = (float4*)(sm + SH_M);
            #pragma unroll
            for (int it = 0; it < 8; it++) dstM[tid + it * 128] = __ldg(Mg + tid + it * 128);
        }
        __syncthreads();

        // GEMM: acc[8 edges][4 out-pairs]
        ull acc[8][4];
        #pragma unroll
        for (int i = 0; i < 8; i++)
            #pragma unroll
            for (int j = 0; j < 4; j++) acc[i][j] = 0ULL;

        #pragma unroll 4
        for (int k = 0; k < 64; k++) {
            ulonglong2 m01 = *(const ulonglong2*)(mB + k * 64);
            ulonglong2 m23 = *(const ulonglong2*)(mB + k * 64 + 4);
            float4 h0 = *(const float4*)(hB + k * 128);
            float4 h1 = *(const float4*)(hB + k * 128 + 4);
            ull hp;
            hp = pk2(h0.x,h0.x);
            acc[0][0]=fma2(m01.x,hp,acc[0][0]); acc[0][1]=fma2(m01.y,hp,acc[0][1]);
            acc[0][2]=fma2(m23.x,hp,acc[0][2]); acc[0][3]=fma2(m23.y,hp,acc[0][3]);
            hp = pk2(h0.y,h0.y);
            acc[1][0]=fma2(m01.x,hp,acc[1][0]); acc[1][1]=fma2(m01.y,hp,acc[1][1]);
            acc[1][2]=fma2(m23.x,hp,acc[1][2]); acc[1][3]=fma2(m23.y,hp,acc[1][3]);
            hp = pk2(h0.z,h0.z);
            acc[2][0]=fma2(m01.x,hp,acc[2][0]); acc[2][1]=fma2(m01.y,hp,acc[2][1]);
            acc[2][2]=fma2(m23.x,hp,acc[2][2]); acc[2][3]=fma2(m23.y,hp,acc[2][3]);
            hp = pk2(h0.w,h0.w);
            acc[3][0]=fma2(m01.x,hp,acc[3][0]); acc[3][1]=fma2(m01.y,hp,acc[3][1]);
            acc[3][2]=fma2(m23.x,hp,acc[3][2]); acc[3][3]=fma2(m23.y,hp,acc[3][3]);
            hp = pk2(h1.x,h1.x);
            acc[4][0]=fma2(m01.x,hp,acc[4][0]); acc[4][1]=fma2(m01.y,hp,acc[4][1]);
            acc[4][2]=fma2(m23.x,hp,acc[4][2]); acc[4][3]=fma2(m23.y,hp,acc[4][3]);
            hp = pk2(h1.y,h1.y);
            acc[5][0]=fma2(m01.x,hp,acc[5][0]); acc[5][1]=fma2(m01.y,hp,acc[5][1]);
            acc[5][2]=fma2(m23.x,hp,acc[5][2]); acc[5][3]=fma2(m23.y,hp,acc[5][3]);
            hp = pk2(h1.z,h1.z);
            acc[6][0]=fma2(m01.x,hp,acc[6][0]); acc[6][1]=fma2(m01.y,hp,acc[6][1]);
            acc[6][2]=fma2(m23.x,hp,acc[6][2]); acc[6][3]=fma2(m23.y,hp,acc[6][3]);
            hp = pk2(h1.w,h1.w);
            acc[7][0]=fma2(m01.x,hp,acc[7][0]); acc[7][1]=fma2(m01.y,hp,acc[7][1]);
            acc[7][2]=fma2(m23.x,hp,acc[7][2]); acc[7][3]=fma2(m23.y,hp,acc[7][3]);
        }

        // store C tile (rows 16B-aligned via C_STRIDE=68)
        #pragma unroll
        for (int i = 0; i < 8; i++) {
            float* cp = sm + SH_C + (eg * 8 + i) * C_STRIDE + og * 8;
            ulonglong2 t0; t0.x = acc[i][0]; t0.y = acc[i][1];
            ulonglong2 t1; t1.x = acc[i][2]; t1.y = acc[i][3];
            *(ulonglong2*)cp = t0;
            *(ulonglong2*)(cp + 4) = t1;
        }
        __syncthreads();

        // epilogue: edge = tid reads g[u][w] for this section
        const float* gC = sm + SH_C + tid * C_STRIDE;
        if (s == 0 || s == 1) {
            #pragma unroll
            for (int u = 0; u < 8; u++) {
                ulonglong2 g01 = *(const ulonglong2*)(gC + u * 8);
                ulonglong2 g23 = *(const ulonglong2*)(gC + u * 8 + 4);
                float f = (s == 1) ? q[u] : p[u];
                ull fp = pk2(f, f);
                outS[0]=fma2(g01.x,fp,outS[0]); outS[1]=fma2(g01.y,fp,outS[1]);
                outS[2]=fma2(g23.x,fp,outS[2]); outS[3]=fma2(g23.y,fp,outS[3]);
            }
        } else if (s == 2 || s == 3) {
            #pragma unroll
            for (int u = 0; u < 8; u++) {
                ulonglong2 g01 = *(const ulonglong2*)(gC + u * 8);
                ulonglong2 g23 = *(const ulonglong2*)(gC + u * 8 + 4);
                float f = (s == 3) ? q[u] : p[u];
                ull fp = pk2(f, f);
                cn[0]=fma2(g01.x,fp,cn[0]); cn[1]=fma2(g01.y,fp,cn[1]);
                cn[2]=fma2(g23.x,fp,cn[2]); cn[3]=fma2(g23.y,fp,cn[3]);
            }
        } else {
            float4 A=xp[2], B=xp[3], C=xp[4], D=xp[5], Ee=xp[6], F=xp[7];
            float xv[8][3];
            xv[0][0]=A.x;  xv[0][1]=A.y;  xv[0][2]=A.z;
            xv[1][0]=A.w;  xv[1][1]=B.x;  xv[1][2]=B.y;
            xv[2][0]=B.z;  xv[2][1]=B.w;  xv[2][2]=C.x;
            xv[3][0]=C.y;  xv[3][1]=C.z;  xv[3][2]=C.w;
            xv[4][0]=D.x;  xv[4][1]=D.y;  xv[4][2]=D.z;
            xv[5][0]=D.w;  xv[5][1]=Ee.x; xv[5][2]=Ee.y;
            xv[6][0]=Ee.z; xv[6][1]=Ee.w; xv[6][2]=F.x;
            xv[7][0]=F.y;  xv[7][1]=F.z;  xv[7][2]=F.w;
            #pragma unroll
            for (int u = 0; u < 8; u++) {
                ulonglong2 g01 = *(const ulonglong2*)(gC + u * 8);
                ulonglong2 g23 = *(const ulonglong2*)(gC + u * 8 + 4);
                #pragma unroll
                for (int k3 = 0; k3 < 3; k3++) {
                    ull fp = pk2(xv[u][k3], xv[u][k3]);
                    oV[k3][0]=fma2(g01.x,fp,oV[k3][0]); oV[k3][1]=fma2(g01.y,fp,oV[k3][1]);
                    oV[k3][2]=fma2(g23.x,fp,oV[k3][2]); oV[k3][3]=fma2(g23.y,fp,oV[k3][3]);
                }
            }
        }
    }

    // n outer-product on accumulated coefficient
    {
        ull nn0 = pk2(nf.x, nf.x), nn1 = pk2(nf.y, nf.y), nn2 = pk2(nf.z, nf.z);
        #pragma unroll
        for (int wp = 0; wp < 4; wp++) {
            oV[0][wp] = fma2(cn[wp], nn0, oV[0][wp]);
            oV[1][wp] = fma2(cn[wp], nn1, oV[1][wp]);
            oV[2][wp] = fma2(cn[wp], nn2, oV[2][wp]);
        }
    }

    if (ve) {
        double* y = g_acc + (size_t)r * 32;
        #pragma unroll
        for (int wp = 0; wp < 4; wp++) {
            float2 sv = upk(outS[wp]);
            atomicAdd(y + wp*2,     (double)sv.x);
            atomicAdd(y + wp*2 + 1, (double)sv.y);
        }
        #pragma unroll
        for (int wp = 0; wp < 4; wp++) {
            #pragma unroll
            for (int k3 = 0; k3 < 3; k3++) {
                float2 vv = upk(oV[k3][wp]);
                atomicAdd(y + 8 + (wp*2)*3   + k3, (double)vv.x);
                atomicAdd(y + 8 + (wp*2+1)*3 + k3, (double)vv.y);
            }
        }
    }
}

extern "C" void kernel_launch(void* const* d_in, const int* in_sizes, int n_in,
                              void* d_out, int out_size)
{
    const float* x   = (const float*)d_in[0];
    const float* pos = (const float*)d_in[1];
    const int*   ei  = (const int*)d_in[2];
    const float* W1  = (const float*)d_in[3];
    const float* W2  = (const float*)d_in[4];
    float* out = (float*)d_out;

    int E = in_sizes[2] / 2;
    int N = in_sizes[1] / 3;

    prep_kernel<<<(M_FLOATS + 255) / 256, 256>>>(W1, W2);
    zero_acc_kernel<<<(N * 32 + 255) / 256, 256>>>(N * 32);
    h_kernel<<<(E + HTH - 1) / HTH, HTH>>>(pos, ei, E);

    int blocks = (E + 127) / 128;
    cudaFuncSetAttribute(edge_kernel, cudaFuncAttributeMaxDynamicSharedMemorySize, SM_TOTAL);
    edge_kernel<<<blocks, GT, SM_TOTAL>>>(x, ei, E);

    finish_kernel<<<(N * 32 + 255) / 256, 256>>>(out, N);
}